// round 17
// baseline (speedup 1.0000x reference)
#include <cuda_runtime.h>
#include <cuda_fp16.h>
#include <cstdint>
#include <cstddef>

#define N_NODES 100000
#define N_EDGES 600000
#define FEAT    128
#define NREL    5
#define NMAT    6
#define NTILES  ((N_NODES + 127) / 128)   // 782
#define NB      (NREL * N_NODES)          // 500000 buckets (rel*N + dst)

// ---------------- device-global scratch ---------------------------------
__device__ __half g_agg[(size_t)NB * FEAT];               // 128 MB aggregates
__device__ __half g_hh[(size_t)N_NODES * FEAT];           // 25.6 MB fp16 h (L2-resident)
__device__ __half g_wfh[NMAT * FEAT * FEAT];              // W^T fp16 [r][n][k]
__device__ int   g_count[NB];
__device__ int   g_cursor[NB];
__device__ int   g_start[NB + 1];
__device__ int2  g_pair[N_EDGES];    // (src, bitcast norm) sorted by (rel,dst)
__device__ int   g_bsum[1024];
__device__ int   g_boff[1024];

// ---------------- helpers ------------------------------------------------
static __device__ __forceinline__ uint32_t smem_u32(const void* p) {
    uint32_t a;
    asm("{ .reg .u64 t; cvta.to.shared.u64 t, %1; cvt.u32.u64 %0, t; }"
        : "=r"(a) : "l"(p));
    return a;
}
static __device__ __forceinline__ uint32_t h2_as_u32(__half2 v) {
    uint32_t u; memcpy(&u, &v, 4); return u;
}
static __device__ __forceinline__ __half2 u32_as_h2(uint32_t u) {
    __half2 v; memcpy(&v, &u, 4); return v;
}

#define LDSM4(r0, r1, r2, r3, a)                                              \
    asm volatile("ldmatrix.sync.aligned.m8n8.x4.shared.b16 {%0,%1,%2,%3}, [%4];" \
                 : "=r"(r0), "=r"(r1), "=r"(r2), "=r"(r3) : "r"(a))

#define MMA_F16(d, a, bb0, bb1)                                               \
    asm volatile("mma.sync.aligned.m16n8k16.row.col.f32.f16.f16.f32 "         \
                 "{%0,%1,%2,%3}, {%4,%5,%6,%7}, {%8,%9}, {%0,%1,%2,%3};"      \
                 : "+f"((d)[0]), "+f"((d)[1]), "+f"((d)[2]), "+f"((d)[3])     \
                 : "r"((a)[0]), "r"((a)[1]), "r"((a)[2]), "r"((a)[3]),        \
                   "r"(bb0), "r"(bb1))

#define MMA_F16ACC(d, a, bb0, bb1)                                            \
    asm volatile("mma.sync.aligned.m16n8k16.row.col.f16.f16.f16.f16 "         \
                 "{%0,%1}, {%2,%3,%4,%5}, {%6,%7}, {%0,%1};"                  \
                 : "+r"((d)[0]), "+r"((d)[1])                                 \
                 : "r"((a)[0]), "r"((a)[1]), "r"((a)[2]), "r"((a)[3]),        \
                   "r"(bb0), "r"(bb1))

#define CP_ASYNC16(dst, src)                                                  \
    asm volatile("cp.async.cg.shared.global [%0], [%1], 16;"                  \
                 :: "r"(dst), "l"(src) : "memory")
#define CP_COMMIT() asm volatile("cp.async.commit_group;" ::: "memory")

#define STG_CS_V2(ptr, x, y)                                                  \
    asm volatile("st.global.cs.v2.u32 [%0], {%1, %2};"                        \
                 :: "l"(ptr), "r"(x), "r"(y) : "memory")

// ---------------- SMEM layout --------------------------------------------
#define APITCH   272u
#define TILE_B   34816u          // 128 rows x 272 B
#define FG_STAGE (2u * TILE_B)   // A + B
#define FG_SMEM  (2u * FG_STAGE) // 139264 (occ 1, 512 thr = 16 warps/SM)
#define W0_SMEM  (2u * TILE_B)

// ============================================================================
// init: weights -> fp16 W^T; zero bucket counters; h -> fp16 g_hh
// ============================================================================
#define ZB  ((NB + 255) / 256)                        // 1954
#define HB  (((N_NODES * FEAT) / 4 + 255) / 256)      // 12500
__global__ void init_kernel(const float* __restrict__ weight,
                            const float* __restrict__ W0,
                            const float* __restrict__ h)
{
    const int b = blockIdx.x;
    if (b < NMAT) {
        const float* src = (b < NREL) ? (weight + (size_t)b * FEAT * FEAT) : W0;
        for (int i = threadIdx.x; i < FEAT * FEAT; i += blockDim.x) {
            const int k = i >> 7, n = i & 127;
            g_wfh[b * FEAT * FEAT + n * FEAT + k] = __float2half_rn(src[k * FEAT + n]);
        }
    } else if (b < NMAT + ZB) {
        const int i = (b - NMAT) * blockDim.x + threadIdx.x;
        if (i < NB) { g_count[i] = 0; g_cursor[i] = 0; }
    } else {
        const int q = (b - NMAT - ZB) * blockDim.x + threadIdx.x;
        const size_t base = (size_t)q * 4;
        if (base < (size_t)N_NODES * FEAT) {
            const float4 v = *reinterpret_cast<const float4*>(h + base);
            uint2 pk;
            pk.x = h2_as_u32(__floats2half2_rn(v.x, v.y));
            pk.y = h2_as_u32(__floats2half2_rn(v.z, v.w));
            *reinterpret_cast<uint2*>(g_hh + base) = pk;
        }
    }
}

// ============================================================================
// CSR over (rel*N + dst) buckets
// ============================================================================
__global__ void hist_kernel(const int* __restrict__ dst,
                            const int* __restrict__ eid) {
    const int e = blockIdx.x * blockDim.x + threadIdx.x;
    if (e < N_EDGES) atomicAdd(&g_count[eid[e] * N_NODES + dst[e]], 1);
}

#define SCAN_NBK ((NB + 511) / 512)    // 977

__global__ __launch_bounds__(512) void scan1_kernel() {
    __shared__ int sh[512];
    const int i = blockIdx.x * 512 + threadIdx.x;
    sh[threadIdx.x] = (i < NB) ? g_count[i] : 0;
    __syncthreads();
    for (int off = 256; off > 0; off >>= 1) {
        if (threadIdx.x < off) sh[threadIdx.x] += sh[threadIdx.x + off];
        __syncthreads();
    }
    if (threadIdx.x == 0) g_bsum[blockIdx.x] = sh[0];
}

__global__ __launch_bounds__(1024) void scan2_kernel() {
    __shared__ int sh[1024];
    const int t = threadIdx.x;
    const int v = (t < SCAN_NBK) ? g_bsum[t] : 0;
    sh[t] = v;
    __syncthreads();
    for (int off = 1; off < 1024; off <<= 1) {
        int x = (t >= off) ? sh[t - off] : 0;
        __syncthreads();
        sh[t] += x;
        __syncthreads();
    }
    if (t < SCAN_NBK) g_boff[t] = sh[t] - v;
    if (t == 1023) g_start[NB] = sh[1023];
}

__global__ __launch_bounds__(512) void scan3_kernel() {
    __shared__ int sh[512];
    const int i = blockIdx.x * 512 + threadIdx.x;
    const int v = (i < NB) ? g_count[i] : 0;
    sh[threadIdx.x] = v;
    __syncthreads();
    for (int off = 1; off < 512; off <<= 1) {
        int x = (threadIdx.x >= off) ? sh[threadIdx.x - off] : 0;
        __syncthreads();
        sh[threadIdx.x] += x;
        __syncthreads();
    }
    if (i < NB) g_start[i] = g_boff[blockIdx.x] + sh[threadIdx.x] - v;
}

__global__ void scatter_kernel(const int* __restrict__ dst,
                               const int* __restrict__ src,
                               const int* __restrict__ eid,
                               const float* __restrict__ norm) {
    const int e = blockIdx.x * blockDim.x + threadIdx.x;
    if (e < N_EDGES) {
        const int b = eid[e] * N_NODES + dst[e];
        const int pos = g_start[b] + atomicAdd(&g_cursor[b], 1);
        g_pair[pos] = make_int2(src[e], __float_as_int(norm[e]));
    }
}

// ============================================================================
// Aggregate: one warp per (rel,dst) bucket. Gathers hit L2-resident g_hh;
// agg rows written with st.cs (evict-first) to protect g_hh in L2.
// ============================================================================
__global__ __launch_bounds__(256) void aggregate_kernel()
{
    const int b    = (blockIdx.x * blockDim.x + threadIdx.x) >> 5;
    const int lane = threadIdx.x & 31;
    if (b >= NB) return;

    int i = g_start[b];
    const int end = g_start[b + 1];

    float4 acc = make_float4(0.f, 0.f, 0.f, 0.f);
    for (; i < end; i++) {
        const int2 p = g_pair[i];
        const float nv = __int_as_float(p.y);
        const uint2 u = reinterpret_cast<const uint2*>(
            g_hh + (size_t)p.x * FEAT)[lane];
        const float2 v0 = __half22float2(u32_as_h2(u.x));
        const float2 v1 = __half22float2(u32_as_h2(u.y));
        acc.x = fmaf(v0.x, nv, acc.x);
        acc.y = fmaf(v0.y, nv, acc.y);
        acc.z = fmaf(v1.x, nv, acc.z);
        acc.w = fmaf(v1.y, nv, acc.w);
    }

    const uint32_t ox = h2_as_u32(__floats2half2_rn(acc.x, acc.y));
    const uint32_t oy = h2_as_u32(__floats2half2_rn(acc.z, acc.w));
    STG_CS_V2(g_agg + (size_t)b * FEAT + lane * 4, ox, oy);
}

// ============================================================================
// Final GEMM: 512 thr, 16 warps (4m x 4n), warp tile m32 x n32, occ 1
// (16 warps/SM). 5 relation GEMMs into ONE fp16 accumulator via 2-stage
// cp.async A(g_agg)+B(g_wfh) pipeline; epilogue: out = relu(out + hsum).
// ============================================================================
__global__ __launch_bounds__(512)
void gemm_final_kernel(float* __restrict__ out)
{
    extern __shared__ __align__(1024) char smem[];
    const uint32_t sb  = smem_u32(smem);
    const int tid  = threadIdx.x;
    const int lane = tid & 31;
    const int warp = tid >> 5;
    const int m_warp = (warp & 3) * 32;
    const int n_warp = (warp >> 2) * 32;
    const int m0 = blockIdx.x * 128;

    const uint32_t a_off = (uint32_t)((((lane >> 3) & 1) * 8 + (lane & 7)) * APITCH
                                      + (lane >> 4) * 16);
    const uint32_t b_off = (uint32_t)((((lane >> 4) * 8) + (lane & 7)) * APITCH
                                      + ((lane >> 3) & 1) * 16);

    // stage 0 (r = 0)
    #pragma unroll
    for (int i = 0; i < 4; i++) {
        const int q   = tid + i * 512;          // 2048 chunks each for A and B
        const int row = q >> 4;
        const int ch  = q & 15;
        const int gm  = min(m0 + row, N_NODES - 1);
        CP_ASYNC16(sb + (uint32_t)(row * APITCH + ch * 16),
                   g_agg + (size_t)gm * FEAT + ch * 8);
        CP_ASYNC16(sb + TILE_B + (uint32_t)(row * APITCH + ch * 16),
                   g_wfh + row * FEAT + ch * 8);
    }
    CP_COMMIT();

    uint32_t facc[2][4][2];
    #pragma unroll
    for (int i = 0; i < 2; i++)
        #pragma unroll
        for (int j = 0; j < 4; j++) { facc[i][j][0] = 0u; facc[i][j][1] = 0u; }

    #pragma unroll 1
    for (int r = 0; r < NREL; r++) {
        const uint32_t stg = sb + (uint32_t)(r & 1) * FG_STAGE;

        if (r + 1 < NREL) {
            const uint32_t nstg = sb + (uint32_t)((r + 1) & 1) * FG_STAGE;
            #pragma unroll
            for (int i = 0; i < 4; i++) {
                const int q   = tid + i * 512;
                const int row = q >> 4;
                const int ch  = q & 15;
                const int gm  = min(m0 + row, N_NODES - 1);
                CP_ASYNC16(nstg + (uint32_t)(row * APITCH + ch * 16),
                           g_agg + ((size_t)(r + 1) * N_NODES + gm) * FEAT + ch * 8);
                CP_ASYNC16(nstg + TILE_B + (uint32_t)(row * APITCH + ch * 16),
                           g_wfh + (size_t)(r + 1) * FEAT * FEAT + row * FEAT + ch * 8);
            }
            CP_COMMIT();
            asm volatile("cp.async.wait_group 1;" ::: "memory");
        } else {
            asm volatile("cp.async.wait_group 0;" ::: "memory");
        }
        __syncthreads();

        const uint32_t aBase = stg + (uint32_t)(m_warp * APITCH) + a_off;
        const uint32_t bBase = stg + TILE_B + (uint32_t)(n_warp * APITCH) + b_off;

        uint32_t ah[2][2][4], bh[2][2][4];
        #pragma unroll
        for (int i = 0; i < 2; i++)
            LDSM4(ah[0][i][0], ah[0][i][1], ah[0][i][2], ah[0][i][3],
                  aBase + (uint32_t)(i * 16 * APITCH));
        #pragma unroll
        for (int j2 = 0; j2 < 2; j2++)
            LDSM4(bh[0][j2][0], bh[0][j2][1], bh[0][j2][2], bh[0][j2][3],
                  bBase + (uint32_t)(j2 * 16 * APITCH));

        #pragma unroll
        for (int ks = 0; ks < 8; ks++) {
            const int cur = ks & 1, nxt = cur ^ 1;
            if (ks < 7) {
                const uint32_t kb = (uint32_t)((ks + 1) * 32);
                #pragma unroll
                for (int i = 0; i < 2; i++)
                    LDSM4(ah[nxt][i][0], ah[nxt][i][1], ah[nxt][i][2], ah[nxt][i][3],
                          aBase + (uint32_t)(i * 16 * APITCH) + kb);
                #pragma unroll
                for (int j2 = 0; j2 < 2; j2++)
                    LDSM4(bh[nxt][j2][0], bh[nxt][j2][1], bh[nxt][j2][2], bh[nxt][j2][3],
                          bBase + (uint32_t)(j2 * 16 * APITCH) + kb);
            }
            #pragma unroll
            for (int i = 0; i < 2; i++) {
                #pragma unroll
                for (int j = 0; j < 4; j++) {
                    const int j2 = j >> 1, jj = (j & 1) * 2;
                    MMA_F16ACC(facc[i][j], ah[cur][i], bh[cur][j2][jj], bh[cur][j2][jj + 1]);
                }
            }
        }
        __syncthreads();
    }

    // epilogue: out = relu(out + hsum)
    #pragma unroll
    for (int i = 0; i < 2; i++) {
        #pragma unroll
        for (int sub = 0; sub < 2; sub++) {
            const int row = m0 + m_warp + i * 16 + sub * 8 + (lane >> 2);
            if (row < N_NODES) {
                #pragma unroll
                for (int j = 0; j < 4; j++) {
                    const int col = n_warp + j * 8 + (lane & 3) * 2;
                    const float2 hs = __half22float2(u32_as_h2(facc[i][j][sub]));
                    float2* op = reinterpret_cast<float2*>(out + (size_t)row * FEAT + col);
                    float2 o = *op;
                    o.x = fmaxf(o.x + hs.x, 0.f);
                    o.y = fmaxf(o.y + hs.y, 0.f);
                    *op = o;
                }
            }
        }
    }
}

// ============================================================================
// W0 GEMM (fp32 acc) -> out. 782 CTAs, 256 thr (proven 22.4us). Side stream.
// ============================================================================
__global__ __launch_bounds__(256, 2)
void gemm_w0_kernel(float* __restrict__ out)
{
    extern __shared__ __align__(1024) char smem[];
    const uint32_t sb  = smem_u32(smem);
    const int tid  = threadIdx.x;
    const int lane = tid & 31;
    const int warp = tid >> 5;
    const int m_warp = (warp & 1) * 64;
    const int n_warp = (warp >> 1) * 32;
    const int m0 = blockIdx.x * 128;

    const uint32_t a_off = (uint32_t)((((lane >> 3) & 1) * 8 + (lane & 7)) * APITCH
                                      + (lane >> 4) * 16);
    const uint32_t b_off = (uint32_t)((((lane >> 4) * 8) + (lane & 7)) * APITCH
                                      + ((lane >> 3) & 1) * 16);

    #pragma unroll
    for (int i = 0; i < 8; i++) {
        const int q   = tid + i * 256;
        const int row = q >> 4;
        const int ch  = q & 15;
        const int gm  = min(m0 + row, N_NODES - 1);
        CP_ASYNC16(sb + (uint32_t)(row * APITCH + ch * 16),
                   g_hh + (size_t)gm * FEAT + ch * 8);
        CP_ASYNC16(sb + TILE_B + (uint32_t)(row * APITCH + ch * 16),
                   g_wfh + (size_t)NREL * FEAT * FEAT + row * FEAT + ch * 8);
    }
    CP_COMMIT();
    asm volatile("cp.async.wait_group 0;" ::: "memory");
    __syncthreads();

    float acc[4][4][4];
    #pragma unroll
    for (int i = 0; i < 4; i++)
        #pragma unroll
        for (int j = 0; j < 4; j++)
            #pragma unroll
            for (int q = 0; q < 4; q++) acc[i][j][q] = 0.f;

    const uint32_t aBase = sb + (uint32_t)(m_warp * APITCH) + a_off;
    const uint32_t bBase = sb + TILE_B + (uint32_t)(n_warp * APITCH) + b_off;

    #pragma unroll
    for (int ks = 0; ks < 8; ks++) {
        const uint32_t kb = (uint32_t)(ks * 32);
        uint32_t ah[4][4], bh[2][4];
        #pragma unroll
        for (int i = 0; i < 4; i++)
            LDSM4(ah[i][0], ah[i][1], ah[i][2], ah[i][3],
                  aBase + (uint32_t)(i * 16 * APITCH) + kb);
        #pragma unroll
        for (int j2 = 0; j2 < 2; j2++)
            LDSM4(bh[j2][0], bh[j2][1], bh[j2][2], bh[j2][3],
                  bBase + (uint32_t)(j2 * 16 * APITCH) + kb);
        #pragma unroll
        for (int i = 0; i < 4; i++) {
            #pragma unroll
            for (int j = 0; j < 4; j++) {
                const int j2 = j >> 1, jj = (j & 1) * 2;
                MMA_F16(acc[i][j], ah[i], bh[j2][jj], bh[j2][jj + 1]);
            }
        }
    }

    #pragma unroll
    for (int i = 0; i < 4; i++) {
        const int row0 = m0 + m_warp + i * 16 + (lane >> 2);
        #pragma unroll
        for (int j = 0; j < 4; j++) {
            const int c = n_warp + j * 8 + (lane & 3) * 2;
            if (row0 < N_NODES)
                *reinterpret_cast<float2*>(out + (size_t)row0 * FEAT + c) =
                    make_float2(acc[i][j][0], acc[i][j][1]);
            if (row0 + 8 < N_NODES)
                *reinterpret_cast<float2*>(out + (size_t)(row0 + 8) * FEAT + c) =
                    make_float2(acc[i][j][2], acc[i][j][3]);
        }
    }
}

// ============================================================================
extern "C" void kernel_launch(void* const* d_in, const int* in_sizes, int n_in,
                              void* d_out, int out_size)
{
    const float* h      = (const float*)d_in[0];
    const float* weight = (const float*)d_in[1];
    const float* W0     = (const float*)d_in[2];
    const float* norm   = (const float*)d_in[3];
    const int*   src    = (const int*)d_in[4];
    const int*   dst    = (const int*)d_in[5];
    const int*   eid    = (const int*)d_in[6];
    float* out = (float*)d_out;
    (void)in_sizes; (void)n_in; (void)out_size;

    cudaFuncSetAttribute(gemm_final_kernel,
                         cudaFuncAttributeMaxDynamicSharedMemorySize, FG_SMEM);
    cudaFuncSetAttribute(gemm_w0_kernel,
                         cudaFuncAttributeMaxDynamicSharedMemorySize, W0_SMEM);

    static cudaStream_t s3 = nullptr;
    static cudaEvent_t  evFork = nullptr, evW0 = nullptr;
    if (s3 == nullptr) {
        if (cudaStreamCreateWithFlags(&s3, cudaStreamNonBlocking) != cudaSuccess)
            s3 = nullptr;
        if (s3) {
            cudaEventCreateWithFlags(&evFork, cudaEventDisableTiming);
            cudaEventCreateWithFlags(&evW0,   cudaEventDisableTiming);
        }
    }

    init_kernel<<<NMAT + ZB + HB, 256>>>(weight, W0, h);

    if (s3) {
        cudaEventRecord(evFork, 0);
        cudaStreamWaitEvent(s3, evFork, 0);
        gemm_w0_kernel<<<NTILES, 256, W0_SMEM, s3>>>(out);   // overlapped
        cudaEventRecord(evW0, s3);

        hist_kernel<<<(N_EDGES + 255) / 256, 256>>>(dst, eid);
        scan1_kernel<<<SCAN_NBK, 512>>>();
        scan2_kernel<<<1, 1024>>>();
        scan3_kernel<<<SCAN_NBK, 512>>>();
        scatter_kernel<<<(N_EDGES + 255) / 256, 256>>>(dst, src, eid, norm);
        aggregate_kernel<<<(NB + 7) / 8, 256>>>();

        cudaStreamWaitEvent(0, evW0, 0);
        gemm_final_kernel<<<NTILES, 512, FG_SMEM>>>(out);
    } else {
        hist_kernel<<<(N_EDGES + 255) / 256, 256>>>(dst, eid);
        scan1_kernel<<<SCAN_NBK, 512>>>();
        scan2_kernel<<<1, 1024>>>();
        scan3_kernel<<<SCAN_NBK, 512>>>();
        scatter_kernel<<<(N_EDGES + 255) / 256, 256>>>(dst, src, eid, norm);
        gemm_w0_kernel<<<NTILES, 256, W0_SMEM>>>(out);
        aggregate_kernel<<<(NB + 7) / 8, 256>>>();
        gemm_final_kernel<<<NTILES, 512, FG_SMEM>>>(out);
    }
}